// round 15
// baseline (speedup 1.0000x reference)
#include <cuda_runtime.h>
#include <cuda_bf16.h>
#include <cstdint>

#define BB      4
#define IN_DIM  8
#define OUT_DIM 64
#define N_WIN   64
#define N_SEQ   4096
#define N_REAL  6144

#define T_TILE  64
#define NTILES  (N_REAL / T_TILE)   // 96
#define THREADS 512

// Precomputed tf32 B fragment table (validated R13 layout):
// word index g = i<<12 | nb<<11 | s<<8 | sl<<7 | lane<<2 | wd. 128KB.
__device__ __align__(16) uint32_t g_Bf[IN_DIM * 2 * 8 * 2 * 32 * 4];

// ---------------- helpers ----------------

__device__ __forceinline__ uint32_t tf32r(float v) {
    uint32_t r;
    asm("cvt.rna.tf32.f32 %0, %1;" : "=r"(r) : "f"(v));
    return r;
}

__device__ __forceinline__ void mma_tf32(float* d, const uint32_t* a, uint32_t b0, uint32_t b1) {
    asm volatile(
        "mma.sync.aligned.m16n8k8.row.col.f32.tf32.tf32.f32 "
        "{%0,%1,%2,%3}, {%4,%5,%6,%7}, {%8,%9}, {%0,%1,%2,%3};"
        : "+f"(d[0]), "+f"(d[1]), "+f"(d[2]), "+f"(d[3])
        : "r"(a[0]), "r"(a[1]), "r"(a[2]), "r"(a[3]), "r"(b0), "r"(b1));
}

// ---------------- weight prep (identical to validated R13) ----------------

__global__ void wprep_frag(const float* __restrict__ w) {
    int g = blockIdx.x * 256 + threadIdx.x;     // 32768 words
    if (g >= IN_DIM * 2 * 8 * 2 * 32 * 4) return;
    int wd   = g & 3;
    int lane = (g >> 2) & 31;
    int sl   = (g >> 7) & 1;
    int s    = (g >> 8) & 7;
    int nb   = (g >> 11) & 1;
    int i    = (g >> 12) & 7;
    int f = 4 * sl + wd;                        // fragment word 0..7
    int c = f >> 1, q = f & 1;
    int o  = 32 * nb + 8 * c + (lane >> 2);
    int kk = 8 * s + (lane & 3) + 4 * q;
    g_Bf[g] = tf32r(w[(o * IN_DIM + i) * N_WIN + (63 - kk)]);
}

// ---------------- main kernel ----------------
// SMEM: zraw 8x128 f32 @0 | bias @4096 | outtile 64x68 f32 @4352
#define SM_ZRAW 0
#define SM_BIAS 4096
#define SM_OUT  4352
#define PITCHW  68
#define SMEM_TOTAL (SM_OUT + OUT_DIM * PITCHW * 4)   // 21760

__global__ __launch_bounds__(THREADS, 2)
void conv_mma(const float* __restrict__ x, const int* __restrict__ srcIdx,
              const float* __restrict__ bias, float* __restrict__ out) {
    extern __shared__ __align__(16) unsigned char smem[];
    float* zraw    = (float*)(smem + SM_ZRAW);
    float* bias_s  = (float*)(smem + SM_BIAS);
    float* outtile = (float*)(smem + SM_OUT);

    const int tid  = threadIdx.x;
    const int wid  = tid >> 5;
    const int lane = tid & 31;
    const int b    = blockIdx.x / NTILES;
    const int t0   = (blockIdx.x % NTILES) * T_TILE;

    if (tid < OUT_DIM) bias_s[tid] = bias[tid];
#pragma unroll
    for (int p = 0; p < 2; p++) zraw[tid + p * THREADS] = 0.f;
    __syncthreads();

    // ---- stage z window [t0-63, t0+63] (127 entries) via parallel scan ----
    {
        const int tlo = t0 - 63;
        const int4* r4 = (const int4*)(srcIdx + b * N_SEQ) + tid * 2;
        const float* xb = x + b * IN_DIM * N_SEQ;
#pragma unroll
        for (int q = 0; q < 2; q++) {
            int4 v = r4[q];
            int s0 = tid * 8 + q * 4;
            int vv[4] = {v.x, v.y, v.z, v.w};
#pragma unroll
            for (int e = 0; e < 4; e++) {
                int tl = vv[e] - tlo;
                if ((unsigned)tl < 127u) {
                    int s = s0 + e;
#pragma unroll
                    for (int i = 0; i < IN_DIM; i++)
                        zraw[i * 128 + tl] = xb[i * N_SEQ + s];
                }
            }
        }
    }
    __syncthreads();

    // ---- round A operand to tf32 (rna) so HW sees exact tf32 values ----
#pragma unroll
    for (int p = 0; p < 2; p++) {
        int e = tid + p * THREADS;
        zraw[e] = __uint_as_float(tf32r(zraw[e]));
    }
    __syncthreads();

    // ---- fragment geometry: warp = (mb2 m32-tile, nb n32-half, ih k-quarter) ----
    const int mb2 = wid & 1;                         // t rows [32mb2, 32mb2+32)
    const int nb  = (wid >> 1) & 1;                  // o half
    const int ih  = wid >> 2;                        // i in {2ih, 2ih+1}
    const int lg  = lane >> 2;
    const int lp4 = lane & 3;
    const int rA  = 32 * mb2 + lg;

    float acc[2][4][4];                              // [m16 subtile][n8 group][frag]
#pragma unroll
    for (int mt = 0; mt < 2; mt++)
#pragma unroll
        for (int c = 0; c < 4; c++)
#pragma unroll
            for (int q = 0; q < 4; q++) acc[mt][c][q] = 0.f;

    // ---- main loop: 2 i x 8 k8-steps, Hankel register sliding window ----
#pragma unroll
    for (int i2 = 0; i2 < 2; i2++) {
        const int i = 2 * ih + i2;
        const float* zi  = zraw + i * 128 + rA + lp4;
        const uint4* bfi = (const uint4*)g_Bf + (i * 2 + nb) * 512 + lane;

        // window: win[j] = z bits at element offset 8s + 4j (init s=0)
        uint32_t win[8];
#pragma unroll
        for (int j = 0; j < 8; j++) win[j] = __float_as_uint(zi[4 * j]);

#pragma unroll
        for (int s = 0; s < 8; s++) {
            const uint4* bp = bfi + s * 64;
            uint4 B0 = bp[0], B1 = bp[32];
            uint32_t bb[8] = {B0.x, B0.y, B0.z, B0.w, B1.x, B1.y, B1.z, B1.w};

            // m16n8k8 A frag: {A[lg][lp4], A[lg+8][lp4], A[lg][lp4+4], A[lg+8][lp4+4]}
            uint32_t a0[4] = {win[0], win[2], win[1], win[3]};   // rows rA..rA+15
            uint32_t a1[4] = {win[4], win[6], win[5], win[7]};   // rows rA+16..rA+31

#pragma unroll
            for (int c = 0; c < 4; c++) mma_tf32(acc[0][c], a0, bb[2 * c], bb[2 * c + 1]);
#pragma unroll
            for (int c = 0; c < 4; c++) mma_tf32(acc[1][c], a1, bb[2 * c], bb[2 * c + 1]);

            if (s < 7) {
                // slide window by one k8-step (8 elements): reuse 6, load 2
#pragma unroll
                for (int j = 0; j < 6; j++) win[j] = win[j + 2];
                win[6] = __float_as_uint(zi[8 * s + 32]);
                win[7] = __float_as_uint(zi[8 * s + 36]);
            }
        }
    }

    // ---- epilogue: combine 4 k-quarters in smem (serialized), add bias, transpose ----
    if (ih == 0) {
#pragma unroll
        for (int mt = 0; mt < 2; mt++)
#pragma unroll
            for (int c = 0; c < 4; c++) {
                int o0 = 32 * nb + 8 * c + 2 * lp4;
                int tl = rA + 16 * mt;
                outtile[o0 * PITCHW + tl]           = acc[mt][c][0] + bias_s[o0];
                outtile[(o0 + 1) * PITCHW + tl]     = acc[mt][c][1] + bias_s[o0 + 1];
                outtile[o0 * PITCHW + tl + 8]       = acc[mt][c][2] + bias_s[o0];
                outtile[(o0 + 1) * PITCHW + tl + 8] = acc[mt][c][3] + bias_s[o0 + 1];
            }
    }
    __syncthreads();
#pragma unroll 1
    for (int ph = 1; ph < 4; ph++) {
        if (ih == ph) {
#pragma unroll
            for (int mt = 0; mt < 2; mt++)
#pragma unroll
                for (int c = 0; c < 4; c++) {
                    int o0 = 32 * nb + 8 * c + 2 * lp4;
                    int tl = rA + 16 * mt;
                    outtile[o0 * PITCHW + tl]           += acc[mt][c][0];
                    outtile[(o0 + 1) * PITCHW + tl]     += acc[mt][c][1];
                    outtile[o0 * PITCHW + tl + 8]       += acc[mt][c][2];
                    outtile[(o0 + 1) * PITCHW + tl + 8] += acc[mt][c][3];
                }
        }
        __syncthreads();
    }

    // ---- coalesced STG.128: 1024 float4 quads, 2 per thread ----
#pragma unroll
    for (int r2 = 0; r2 < 2; r2++) {
        int u  = tid + r2 * THREADS;                 // 0..1023
        int o  = u >> 4;
        int tq = u & 15;
        float4 v = *(float4*)(outtile + o * PITCHW + 4 * tq);
        *(float4*)(out + (b * OUT_DIM + o) * N_REAL + t0 + 4 * tq) = v;
    }
}

// ---------------- launch ----------------

extern "C" void kernel_launch(void* const* d_in, const int* in_sizes, int n_in,
                              void* d_out, int out_size) {
    const float* x      = (const float*)d_in[0];   // (4, 8, 4096)
    const float* weight = (const float*)d_in[1];   // (64, 8, 64)
    const float* bias   = (const float*)d_in[2];   // (64,)
    const int*   srcIdx = (const int*)d_in[3];     // (4, 4096)
    float*       out    = (float*)d_out;           // (4, 64, 6144)

    static bool attr_done = false;
    if (!attr_done) {
        cudaFuncSetAttribute(conv_mma, cudaFuncAttributeMaxDynamicSharedMemorySize, SMEM_TOTAL);
        attr_done = true;
    }

    wprep_frag<<<(IN_DIM * 2 * 8 * 2 * 32 * 4 + 255) / 256, 256>>>(weight);
    conv_mma<<<BB * NTILES, THREADS, SMEM_TOTAL>>>(x, srcIdx, bias, out);
}

// round 16
// speedup vs baseline: 1.1509x; 1.1509x over previous
#include <cuda_runtime.h>
#include <cuda_bf16.h>
#include <cstdint>

#define BB      4
#define IN_DIM  8
#define OUT_DIM 64
#define N_WIN   64
#define N_SEQ   4096
#define N_REAL  6144

#define T_TILE  64
#define NTILES  (N_REAL / T_TILE)   // 96
#define THREADS 256

// tf32 B fragment table: uint4 per (i, nq, s, lane) = fragment for n8 groups {2nq.., } :
// words = (c0,q0),(c0,q1),(c1,q0),(c1,q1). 8*4*8*32 uint4 = 128KB.
__device__ __align__(16) uint4 g_Bf[IN_DIM * 4 * 8 * 32];

// ---------------- helpers ----------------

__device__ __forceinline__ uint32_t tf32r(float v) {
    uint32_t r;
    asm("cvt.rna.tf32.f32 %0, %1;" : "=r"(r) : "f"(v));
    return r;
}

__device__ __forceinline__ void mma_tf32(float* d, const uint32_t* a, uint32_t b0, uint32_t b1) {
    asm volatile(
        "mma.sync.aligned.m16n8k8.row.col.f32.tf32.tf32.f32 "
        "{%0,%1,%2,%3}, {%4,%5,%6,%7}, {%8,%9}, {%0,%1,%2,%3};"
        : "+f"(d[0]), "+f"(d[1]), "+f"(d[2]), "+f"(d[3])
        : "r"(a[0]), "r"(a[1]), "r"(a[2]), "r"(a[3]), "r"(b0), "r"(b1));
}

// ---------------- weight prep: per-lane tf32 B fragments (n16 granularity) ----------------
// B[k][o] = W[o][i][63-k]. m16n8k8 col-B frag, n8 group c, reg q:
//   word of lane l = B[8s + l%4 + 4q][16nq + 8c + l/4].

__global__ void wprep_frag(const float* __restrict__ w) {
    int g = blockIdx.x * 256 + threadIdx.x;     // 8192 uint4 entries
    if (g >= IN_DIM * 4 * 8 * 32) return;
    int lane = g & 31;
    int s    = (g >> 5) & 7;
    int nq   = (g >> 8) & 3;
    int i    = (g >> 10) & 7;
    int lg = lane >> 2, lp4 = lane & 3;
    uint32_t wv[4];
#pragma unroll
    for (int wd = 0; wd < 4; wd++) {
        int c = wd >> 1, q = wd & 1;
        int o  = 16 * nq + 8 * c + lg;
        int kk = 8 * s + lp4 + 4 * q;
        wv[wd] = tf32r(w[(o * IN_DIM + i) * N_WIN + (63 - kk)]);
    }
    g_Bf[g] = make_uint4(wv[0], wv[1], wv[2], wv[3]);
}

// ---------------- main kernel ----------------
// SMEM: zraw 8x128 f32 @0 | bias @4096 | outtile 64x68 f32 @4352
#define SM_ZRAW 0
#define SM_BIAS 4096
#define SM_OUT  4352
#define PITCHW  68
#define SMEM_TOTAL (SM_OUT + OUT_DIM * PITCHW * 4)   // 21760

__global__ __launch_bounds__(THREADS, 3)
void conv_mma(const float* __restrict__ x, const int* __restrict__ srcIdx,
              const float* __restrict__ bias, float* __restrict__ out) {
    extern __shared__ __align__(16) unsigned char smem[];
    float* zraw    = (float*)(smem + SM_ZRAW);
    float* bias_s  = (float*)(smem + SM_BIAS);
    float* outtile = (float*)(smem + SM_OUT);

    const int tid  = threadIdx.x;
    const int wid  = tid >> 5;
    const int lane = tid & 31;
    const int b    = blockIdx.x / NTILES;
    const int t0   = (blockIdx.x % NTILES) * T_TILE;

    if (tid < OUT_DIM) bias_s[tid] = bias[tid];
#pragma unroll
    for (int p = 0; p < 4; p++) zraw[tid + p * THREADS] = 0.f;
    __syncthreads();

    // ---- stage z window [t0-63, t0+63] (127 entries) via parallel scan ----
    {
        const int tlo = t0 - 63;
        const int4* r4 = (const int4*)(srcIdx + b * N_SEQ) + tid * 4;
        const float* xb = x + b * IN_DIM * N_SEQ;
#pragma unroll
        for (int q = 0; q < 4; q++) {
            int4 v = r4[q];
            int s0 = tid * 16 + q * 4;
            int vv[4] = {v.x, v.y, v.z, v.w};
#pragma unroll
            for (int e = 0; e < 4; e++) {
                int tl = vv[e] - tlo;
                if ((unsigned)tl < 127u) {
                    int s = s0 + e;
#pragma unroll
                    for (int i = 0; i < IN_DIM; i++)
                        zraw[i * 128 + tl] = xb[i * N_SEQ + s];
                }
            }
        }
    }
    __syncthreads();

    // ---- round A operand to tf32 (rna) so HW sees exact tf32 values ----
#pragma unroll
    for (int p = 0; p < 4; p++) {
        int e = tid + p * THREADS;
        zraw[e] = __uint_as_float(tf32r(zraw[e]));
    }
    __syncthreads();

    // ---- fragment geometry: warp = (nq n16-quarter, ih k-half); m64 per warp ----
    const int nq  = wid & 3;                         // o in [16nq, 16nq+16)
    const int ih  = wid >> 2;                        // i in [4ih, 4ih+4)
    const int lg  = lane >> 2;
    const int lp4 = lane & 3;

    float acc[4][2][4];                              // [m16 tile][n8 group][frag]
#pragma unroll
    for (int mt = 0; mt < 4; mt++)
#pragma unroll
        for (int c = 0; c < 2; c++)
#pragma unroll
            for (int q = 0; q < 4; q++) acc[mt][c][q] = 0.f;

    // ---- main loop: 4 i x 8 k8-steps; rotating 16-word Hankel window, static indices ----
#pragma unroll 1
    for (int i2 = 0; i2 < 4; i2++) {
        const int i = 4 * ih + i2;
        const float* zi  = zraw + i * 128 + lg + lp4;
        const uint4* bfi = g_Bf + (i * 4 + nq) * 256 + lane;

        // invariant at step s: win[(j + 2s) & 15] = zi[8s + 4j]
        uint32_t win[16];
#pragma unroll
        for (int j = 0; j < 16; j++) win[j] = __float_as_uint(zi[4 * j]);

#pragma unroll
        for (int s = 0; s < 8; s++) {
            uint4 B = bfi[s * 32];

#pragma unroll
            for (int mt = 0; mt < 4; mt++) {
                // A frag offsets {0,8,4,12}+16mt+8s -> j = 4mt + {0,2,1,3}
                uint32_t a[4] = {win[(4 * mt + 0 + 2 * s) & 15],
                                 win[(4 * mt + 2 + 2 * s) & 15],
                                 win[(4 * mt + 1 + 2 * s) & 15],
                                 win[(4 * mt + 3 + 2 * s) & 15]};
                mma_tf32(acc[mt][0], a, B.x, B.y);
                mma_tf32(acc[mt][1], a, B.z, B.w);
            }

            if (s < 7) {
                // two new words for step s+1 (slots freed by j=0,1 of step s)
                win[(2 * s + 0) & 15] = __float_as_uint(zi[8 * s + 64]);
                win[(2 * s + 1) & 15] = __float_as_uint(zi[8 * s + 68]);
            }
        }
    }

    // ---- epilogue: combine k-halves in smem, add bias, transpose ----
    if (ih == 0) {
#pragma unroll
        for (int mt = 0; mt < 4; mt++)
#pragma unroll
            for (int c = 0; c < 2; c++) {
                int o0 = 16 * nq + 8 * c + 2 * lp4;
                int tl = 16 * mt + lg;
                outtile[o0 * PITCHW + tl]           = acc[mt][c][0] + bias_s[o0];
                outtile[(o0 + 1) * PITCHW + tl]     = acc[mt][c][1] + bias_s[o0 + 1];
                outtile[o0 * PITCHW + tl + 8]       = acc[mt][c][2] + bias_s[o0];
                outtile[(o0 + 1) * PITCHW + tl + 8] = acc[mt][c][3] + bias_s[o0 + 1];
            }
    }
    __syncthreads();
    if (ih == 1) {
#pragma unroll
        for (int mt = 0; mt < 4; mt++)
#pragma unroll
            for (int c = 0; c < 2; c++) {
                int o0 = 16 * nq + 8 * c + 2 * lp4;
                int tl = 16 * mt + lg;
                outtile[o0 * PITCHW + tl]           += acc[mt][c][0];
                outtile[(o0 + 1) * PITCHW + tl]     += acc[mt][c][1];
                outtile[o0 * PITCHW + tl + 8]       += acc[mt][c][2];
                outtile[(o0 + 1) * PITCHW + tl + 8] += acc[mt][c][3];
            }
    }
    __syncthreads();

    // ---- coalesced STG.128: 1024 float4 quads, 4 per thread ----
#pragma unroll
    for (int r2 = 0; r2 < 4; r2++) {
        int u  = tid + r2 * THREADS;                 // 0..1023
        int o  = u >> 4;
        int tq = u & 15;
        float4 v = *(float4*)(outtile + o * PITCHW + 4 * tq);
        *(float4*)(out + (b * OUT_DIM + o) * N_REAL + t0 + 4 * tq) = v;
    }
}

// ---------------- launch ----------------

extern "C" void kernel_launch(void* const* d_in, const int* in_sizes, int n_in,
                              void* d_out, int out_size) {
    const float* x      = (const float*)d_in[0];   // (4, 8, 4096)
    const float* weight = (const float*)d_in[1];   // (64, 8, 64)
    const float* bias   = (const float*)d_in[2];   // (64,)
    const int*   srcIdx = (const int*)d_in[3];     // (4, 4096)
    float*       out    = (float*)d_out;           // (4, 64, 6144)

    static bool attr_done = false;
    if (!attr_done) {
        cudaFuncSetAttribute(conv_mma, cudaFuncAttributeMaxDynamicSharedMemorySize, SMEM_TOTAL);
        attr_done = true;
    }

    wprep_frag<<<(IN_DIM * 4 * 8 * 32 + 255) / 256, 256>>>(weight);
    conv_mma<<<BB * NTILES, THREADS, SMEM_TOTAL>>>(x, srcIdx, bias, out);
}

// round 17
// speedup vs baseline: 1.2753x; 1.1081x over previous
#include <cuda_runtime.h>
#include <cuda_bf16.h>
#include <cstdint>

#define BB      4
#define IN_DIM  8
#define OUT_DIM 64
#define N_WIN   64
#define N_SEQ   4096
#define N_REAL  6144

#define T_TILE  64
#define NTILES  (N_REAL / T_TILE)   // 96
#define THREADS 256

// tf32 B fragment table (validated R15 layout): uint4 per (i, nq, s, lane).
__device__ __align__(16) uint4 g_Bf[IN_DIM * 4 * 8 * 32];

// ---------------- helpers ----------------

__device__ __forceinline__ uint32_t tf32r(float v) {
    uint32_t r;
    asm("cvt.rna.tf32.f32 %0, %1;" : "=r"(r) : "f"(v));
    return r;
}

__device__ __forceinline__ void mma_tf32(float* d, const uint32_t* a, uint32_t b0, uint32_t b1) {
    asm volatile(
        "mma.sync.aligned.m16n8k8.row.col.f32.tf32.tf32.f32 "
        "{%0,%1,%2,%3}, {%4,%5,%6,%7}, {%8,%9}, {%0,%1,%2,%3};"
        : "+f"(d[0]), "+f"(d[1]), "+f"(d[2]), "+f"(d[3])
        : "r"(a[0]), "r"(a[1]), "r"(a[2]), "r"(a[3]), "r"(b0), "r"(b1));
}

// ---------------- weight prep (identical to validated R15) ----------------

__global__ void wprep_frag(const float* __restrict__ w) {
    int g = blockIdx.x * 256 + threadIdx.x;     // 8192 uint4 entries
    if (g >= IN_DIM * 4 * 8 * 32) return;
    int lane = g & 31;
    int s    = (g >> 5) & 7;
    int nq   = (g >> 8) & 3;
    int i    = (g >> 10) & 7;
    int lg = lane >> 2, lp4 = lane & 3;
    uint32_t wv[4];
#pragma unroll
    for (int wd = 0; wd < 4; wd++) {
        int c = wd >> 1, q = wd & 1;
        int o  = 16 * nq + 8 * c + lg;
        int kk = 8 * s + lp4 + 4 * q;
        wv[wd] = tf32r(w[(o * IN_DIM + i) * N_WIN + (63 - kk)]);
    }
    g_Bf[g] = make_uint4(wv[0], wv[1], wv[2], wv[3]);
}

// ---------------- main kernel ----------------
// SMEM: zraw 8x128 f32 @0 | bias @4096 | outtileA 64x68 f32 @4352 | outtileB @21760
#define SM_ZRAW 0
#define SM_BIAS 4096
#define SM_OUTA 4352
#define SM_OUTB (SM_OUTA + OUT_DIM * 68 * 4)          // 21760
#define PITCHW  68
#define SMEM_TOTAL (SM_OUTB + OUT_DIM * 68 * 4)       // 39168

__global__ __launch_bounds__(THREADS, 3)
void conv_mma(const float* __restrict__ x, const int* __restrict__ srcIdx,
              const float* __restrict__ bias, float* __restrict__ out) {
    extern __shared__ __align__(16) unsigned char smem[];
    float* zraw   = (float*)(smem + SM_ZRAW);
    float* bias_s = (float*)(smem + SM_BIAS);
    float* outA   = (float*)(smem + SM_OUTA);
    float* outB   = (float*)(smem + SM_OUTB);

    const int tid  = threadIdx.x;
    const int wid  = tid >> 5;
    const int lane = tid & 31;
    const int b    = blockIdx.x / NTILES;
    const int t0   = (blockIdx.x % NTILES) * T_TILE;

    if (tid < OUT_DIM) bias_s[tid] = bias[tid];
#pragma unroll
    for (int p = 0; p < 4; p++) zraw[tid + p * THREADS] = 0.f;
    __syncthreads();

    // ---- stage z window [t0-63, t0+63] via parallel scan; tf32-round at write ----
    {
        const int tlo = t0 - 63;
        const int4* r4 = (const int4*)(srcIdx + b * N_SEQ) + tid * 4;
        const float* xb = x + b * IN_DIM * N_SEQ;
#pragma unroll
        for (int q = 0; q < 4; q++) {
            int4 v = r4[q];
            int s0 = tid * 16 + q * 4;
            int vv[4] = {v.x, v.y, v.z, v.w};
#pragma unroll
            for (int e = 0; e < 4; e++) {
                int tl = vv[e] - tlo;
                if ((unsigned)tl < 127u) {
                    int s = s0 + e;
#pragma unroll
                    for (int i = 0; i < IN_DIM; i++)
                        zraw[i * 128 + tl] =
                            __uint_as_float(tf32r(xb[i * N_SEQ + s]));
                }
            }
        }
    }
    __syncthreads();

    // ---- fragment geometry: warp = (nq n16-quarter, ih k-half); m64 per warp ----
    const int nq  = wid & 3;                         // o in [16nq, 16nq+16)
    const int ih  = wid >> 2;                        // i in [4ih, 4ih+4)
    const int lg  = lane >> 2;
    const int lp4 = lane & 3;

    float acc[4][2][4];                              // [m16 tile][n8 group][frag]
#pragma unroll
    for (int mt = 0; mt < 4; mt++)
#pragma unroll
        for (int c = 0; c < 2; c++)
#pragma unroll
            for (int q = 0; q < 4; q++) acc[mt][c][q] = 0.f;

    // ---- main loop: 4 i x 8 k8-steps; rotating 16-word Hankel window, static indices ----
#pragma unroll 2
    for (int i2 = 0; i2 < 4; i2++) {
        const int i = 4 * ih + i2;
        const float* zi  = zraw + i * 128 + lg + lp4;
        const uint4* bfi = g_Bf + (i * 4 + nq) * 256 + lane;

        // invariant at step s: win[(j + 2s) & 15] = zi[8s + 4j]
        uint32_t win[16];
#pragma unroll
        for (int j = 0; j < 16; j++) win[j] = __float_as_uint(zi[4 * j]);

#pragma unroll
        for (int s = 0; s < 8; s++) {
            uint4 B = bfi[s * 32];

#pragma unroll
            for (int mt = 0; mt < 4; mt++) {
                // A frag offsets {0,8,4,12}+16mt+8s -> j = 4mt + {0,2,1,3}
                uint32_t a[4] = {win[(4 * mt + 0 + 2 * s) & 15],
                                 win[(4 * mt + 2 + 2 * s) & 15],
                                 win[(4 * mt + 1 + 2 * s) & 15],
                                 win[(4 * mt + 3 + 2 * s) & 15]};
                mma_tf32(acc[mt][0], a, B.x, B.y);
                mma_tf32(acc[mt][1], a, B.z, B.w);
            }

            if (s < 7) {
                // two new words for step s+1 (slots freed by j=0,1 of step s)
                win[(2 * s + 0) & 15] = __float_as_uint(zi[8 * s + 64]);
                win[(2 * s + 1) & 15] = __float_as_uint(zi[8 * s + 68]);
            }
        }
    }

    // ---- epilogue: both k-halves write concurrently to separate buffers ----
    {
        float* obuf = (ih == 0) ? outA : outB;
#pragma unroll
        for (int mt = 0; mt < 4; mt++)
#pragma unroll
            for (int c = 0; c < 2; c++) {
                int o0 = 16 * nq + 8 * c + 2 * lp4;
                int tl = 16 * mt + lg;
                float b0 = (ih == 0) ? bias_s[o0]     : 0.f;
                float b1 = (ih == 0) ? bias_s[o0 + 1] : 0.f;
                obuf[o0 * PITCHW + tl]           = acc[mt][c][0] + b0;
                obuf[(o0 + 1) * PITCHW + tl]     = acc[mt][c][1] + b1;
                obuf[o0 * PITCHW + tl + 8]       = acc[mt][c][2] + b0;
                obuf[(o0 + 1) * PITCHW + tl + 8] = acc[mt][c][3] + b1;
            }
    }
    __syncthreads();

    // ---- combine + coalesced STG.128: 1024 float4 quads, 4 per thread ----
#pragma unroll
    for (int r2 = 0; r2 < 4; r2++) {
        int u  = tid + r2 * THREADS;                 // 0..1023
        int o  = u >> 4;
        int tq = u & 15;
        const float* pa = outA + o * PITCHW + 4 * tq;
        const float* pb = outB + o * PITCHW + 4 * tq;
        float4 va = *(const float4*)pa;
        float4 vb = *(const float4*)pb;
        float4 v = make_float4(va.x + vb.x, va.y + vb.y, va.z + vb.z, va.w + vb.w);
        *(float4*)(out + (b * OUT_DIM + o) * N_REAL + t0 + 4 * tq) = v;
    }
}

// ---------------- launch ----------------

extern "C" void kernel_launch(void* const* d_in, const int* in_sizes, int n_in,
                              void* d_out, int out_size) {
    const float* x      = (const float*)d_in[0];   // (4, 8, 4096)
    const float* weight = (const float*)d_in[1];   // (64, 8, 64)
    const float* bias   = (const float*)d_in[2];   // (64,)
    const int*   srcIdx = (const int*)d_in[3];     // (4, 4096)
    float*       out    = (float*)d_out;           // (4, 64, 6144)

    static bool attr_done = false;
    if (!attr_done) {
        cudaFuncSetAttribute(conv_mma, cudaFuncAttributeMaxDynamicSharedMemorySize, SMEM_TOTAL);
        attr_done = true;
    }

    wprep_frag<<<(IN_DIM * 4 * 8 * 32 + 255) / 256, 256>>>(weight);
    conv_mma<<<BB * NTILES, THREADS, SMEM_TOTAL>>>(x, srcIdx, bias, out);
}